// round 11
// baseline (speedup 1.0000x reference)
#include <cuda_runtime.h>
#include <cuda_bf16.h>
#include <cstdint>
#include <math.h>

// ---------------- problem constants ----------------
#define E_DIM  1024
#define H_NUM  16
#define DK_    64
#define B_SZ   2
#define S_LEN  2048
#define M_TOK  (B_SZ * S_LEN)
#define N_QKV  (3 * E_DIM)
#define K_DIM  1024

#define QSCALE (0.125f * 1.44269504088896f)   // 1/sqrt(dk) * log2(e)

// ---------------- device scratch (alloc-free) ----------------
__device__ __align__(16) __nv_bfloat16 g_xb[M_TOK * K_DIM];
__device__ __align__(16) __nv_bfloat16 g_wqb[N_QKV * K_DIM];
__device__ __align__(16) __nv_bfloat16 g_wcb[E_DIM * K_DIM];
__device__ __align__(16) __nv_bfloat16 g_qb[B_SZ * H_NUM * S_LEN * DK_];
__device__ __align__(16) __nv_bfloat16 g_kb[B_SZ * H_NUM * S_LEN * DK_];
__device__ __align__(16) __nv_bfloat16 g_vTb[B_SZ * H_NUM * DK_ * S_LEN];
__device__ __align__(16) __nv_bfloat16 g_attnb[M_TOK * E_DIM];
__device__ float g_proj[M_TOK * E_DIM];

__device__ __forceinline__ uint32_t packbf(float lo, float hi) {
    uint32_t r;
    asm("cvt.rn.bf16x2.f32 %0, %1, %2;" : "=r"(r) : "f"(hi), "f"(lo));
    return r;
}
__device__ __forceinline__ void mma_bf16(float c[4], const uint32_t a[4],
                                         const uint32_t b0, const uint32_t b1) {
    asm volatile(
        "mma.sync.aligned.m16n8k16.row.col.f32.bf16.bf16.f32 "
        "{%0,%1,%2,%3}, {%4,%5,%6,%7}, {%8,%9}, {%0,%1,%2,%3};"
        : "+f"(c[0]), "+f"(c[1]), "+f"(c[2]), "+f"(c[3])
        : "r"(a[0]), "r"(a[1]), "r"(a[2]), "r"(a[3]), "r"(b0), "r"(b1));
}
__device__ __forceinline__ void ldm_x4(uint32_t& r0, uint32_t& r1,
                                       uint32_t& r2, uint32_t& r3, uint32_t a) {
    asm volatile("ldmatrix.sync.aligned.m8n8.x4.shared.b16 {%0,%1,%2,%3}, [%4];"
                 : "=r"(r0), "=r"(r1), "=r"(r2), "=r"(r3) : "r"(a));
}
__device__ __forceinline__ void cp16(uint32_t dst, const void* src) {
    asm volatile("cp.async.cg.shared.global [%0], [%1], 16;"
                 :: "r"(dst), "l"(src));
}
#define CP_COMMIT() asm volatile("cp.async.commit_group;")
#define CP_WAIT0()  asm volatile("cp.async.wait_group 0;")

// ======================================================================
// fp32 -> bf16 bulk convert
// ======================================================================
__global__ __launch_bounds__(256) void conv_bf16(const float* __restrict__ src,
                                                 __nv_bfloat16* __restrict__ dst,
                                                 int n8)
{
    int i = blockIdx.x * 256 + threadIdx.x;
    if (i >= n8) return;
    float4 a = *(const float4*)&src[i * 8];
    float4 b = *(const float4*)&src[i * 8 + 4];
    uint4 o = make_uint4(packbf(a.x, a.y), packbf(a.z, a.w),
                         packbf(b.x, b.y), packbf(b.z, b.w));
    *(uint4*)&dst[i * 8] = o;
}

// ======================================================================
// bf16 GEMM, occupancy-optimized: CTA 128x64, BK=64, 2-stage cp.async,
// ldmatrix fragments, one barrier per chunk, 3 CTAs/SM.
// 8 warps in 4m x 2n; warp tile 32x32 (mt=2 m16, nt=4 n8).
// Smem row stride 144B (128B data + 16B pad): bank unit (row+chunk)%8
//   => conflict-free ldmatrix, 16B-aligned cp.async.
// MODE 0: A=g_xb, W=g_wqb -> g_qb(xQSCALE)/g_kb/g_vTb
// MODE 1: A=g_attnb, W=g_wcb, +bias -> fp32 g_proj
// ======================================================================
#define ROWB 144
#define A_MATB (128 * ROWB)               // 18432
#define B_MATB (64 * ROWB)                // 9216
#define STAGEB (A_MATB + B_MATB)          // 27648
#define GEMM_SMEM_BYTES (2 * STAGEB)      // 55296

template <int MODE>
__global__ __launch_bounds__(256, 3) void gemm_cp(const float* __restrict__ bias)
{
    extern __shared__ char sm[];
    const uint32_t smbase = (uint32_t)__cvta_generic_to_shared(sm);

    const __nv_bfloat16* __restrict__ A = (MODE == 1) ? g_attnb : g_xb;
    const __nv_bfloat16* __restrict__ W = (MODE == 1) ? g_wcb : g_wqb;

    const int tid = threadIdx.x;
    const int wid = tid >> 5;
    const int lane = tid & 31;
    const int mu = lane >> 2;
    const int la = lane & 3;
    const int warp_m = wid & 3;            // 4 m-groups of 32 rows
    const int warp_n = wid >> 2;           // 2 n-groups of 32 cols
    const int m0 = blockIdx.y * 128;
    const int n0 = blockIdx.x * 64;

    // staging A: thread -> row tid>>1 (0..127), chunk group (tid&1)*4 (4 cp16)
    const int ar = tid >> 1;
    const int ac = (tid & 1) * 4;
    const __nv_bfloat16* asrc = &A[(size_t)(m0 + ar) * K_DIM + ac * 8];
    const uint32_t a_off = (uint32_t)(ar * ROWB + ac * 16);
    // staging B: thread -> row tid>>2 (0..63), chunk group (tid&3)*2 (2 cp16)
    const int br = tid >> 2;
    const int bc = (tid & 3) * 2;
    const __nv_bfloat16* wsrc = &W[(size_t)(n0 + br) * K_DIM + bc * 8];
    const uint32_t b_off = (uint32_t)(A_MATB + br * ROWB + bc * 16);

    const int lrow = lane & 15;
    const int lchunk = lane >> 4;

    float acc[2][4][4];
#pragma unroll
    for (int mt = 0; mt < 2; mt++)
#pragma unroll
        for (int nt = 0; nt < 4; nt++)
#pragma unroll
            for (int e = 0; e < 4; e++) acc[mt][nt][e] = 0.f;

    const int NK = K_DIM / 64;             // 16

    // ---- prologue: stage 0 ----
    {
        uint32_t ad = smbase + a_off;
#pragma unroll
        for (int i = 0; i < 4; i++) cp16(ad + i * 16, asrc + i * 8);
        uint32_t bd = smbase + b_off;
#pragma unroll
        for (int i = 0; i < 2; i++) cp16(bd + i * 16, wsrc + i * 8);
        CP_COMMIT();
    }

    for (int t = 0; t < NK; t++) {
        CP_WAIT0();                        // stage t landed
        __syncthreads();                   // also proves stage t^1 reads done

        if (t + 1 < NK) {
            const uint32_t stb = smbase + ((t + 1) & 1) * STAGEB;
            const int k0 = (t + 1) * 64;
            uint32_t ad = stb + a_off;
#pragma unroll
            for (int i = 0; i < 4; i++) cp16(ad + i * 16, asrc + k0 + i * 8);
            uint32_t bd = stb + b_off;
#pragma unroll
            for (int i = 0; i < 2; i++) cp16(bd + i * 16, wsrc + k0 + i * 8);
            CP_COMMIT();
        }

        const uint32_t abase = smbase + (t & 1) * STAGEB;
        const uint32_t bbase = abase + A_MATB;

#pragma unroll
        for (int kk = 0; kk < 4; kk++) {
            uint32_t afr[2][4];
#pragma unroll
            for (int mt = 0; mt < 2; mt++) {
                const int row = warp_m * 32 + mt * 16 + lrow;
                ldm_x4(afr[mt][0], afr[mt][1], afr[mt][2], afr[mt][3],
                       abase + row * ROWB + (kk * 2 + lchunk) * 16);
            }
            uint32_t bfr[4][2];
#pragma unroll
            for (int np = 0; np < 2; np++) {
                const int row = warp_n * 32 + np * 16 + lrow;
                uint32_t b0, b1, b2, b3;
                ldm_x4(b0, b1, b2, b3,
                       bbase + row * ROWB + (kk * 2 + lchunk) * 16);
                bfr[2 * np][0] = b0;     bfr[2 * np][1] = b2;
                bfr[2 * np + 1][0] = b1; bfr[2 * np + 1][1] = b3;
            }
#pragma unroll
            for (int mt = 0; mt < 2; mt++)
#pragma unroll
                for (int nt = 0; nt < 4; nt++)
                    mma_bf16(acc[mt][nt], afr[mt], bfr[nt][0], bfr[nt][1]);
        }
    }

    // ---- epilogue ----
#pragma unroll
    for (int mt = 0; mt < 2; mt++) {
        const int m_lo = m0 + warp_m * 32 + mt * 16 + mu;
        const int m_hi = m_lo + 8;
#pragma unroll
        for (int nt = 0; nt < 4; nt++) {
            const int n = n0 + warp_n * 32 + nt * 8 + 2 * la;
            if (MODE == 0) {
                const int which = n >> 10;
                const int h = (n >> 6) & 15;
                const int d0 = n & 63;
                const int b = m_lo >> 11;
                const int s_lo = m_lo & 2047, s_hi = m_hi & 2047;
                if (which == 0) {
                    size_t base = (((size_t)(b * H_NUM + h)) * S_LEN);
                    *(uint32_t*)&g_qb[(base + s_lo) * DK_ + d0] =
                        packbf(acc[mt][nt][0] * QSCALE, acc[mt][nt][1] * QSCALE);
                    *(uint32_t*)&g_qb[(base + s_hi) * DK_ + d0] =
                        packbf(acc[mt][nt][2] * QSCALE, acc[mt][nt][3] * QSCALE);
                } else if (which == 1) {
                    size_t base = (((size_t)(b * H_NUM + h)) * S_LEN);
                    *(uint32_t*)&g_kb[(base + s_lo) * DK_ + d0] =
                        packbf(acc[mt][nt][0], acc[mt][nt][1]);
                    *(uint32_t*)&g_kb[(base + s_hi) * DK_ + d0] =
                        packbf(acc[mt][nt][2], acc[mt][nt][3]);
                } else {
                    size_t base = (((size_t)(b * H_NUM + h)) * DK_ + d0) * S_LEN;
                    g_vTb[base + s_lo]          = __float2bfloat16_rn(acc[mt][nt][0]);
                    g_vTb[base + S_LEN + s_lo]  = __float2bfloat16_rn(acc[mt][nt][1]);
                    g_vTb[base + s_hi]          = __float2bfloat16_rn(acc[mt][nt][2]);
                    g_vTb[base + S_LEN + s_hi]  = __float2bfloat16_rn(acc[mt][nt][3]);
                }
            } else {
                const float b0 = bias[n], b1 = bias[n + 1];
                *(float2*)&g_proj[(size_t)m_lo * E_DIM + n] =
                    make_float2(acc[mt][nt][0] + b0, acc[mt][nt][1] + b1);
                *(float2*)&g_proj[(size_t)m_hi * E_DIM + n] =
                    make_float2(acc[mt][nt][2] + b0, acc[mt][nt][3] + b1);
            }
        }
    }
}

// ======================================================================
// Flash attention, bf16 m16n8k16, register-resident P (unchanged, passing).
// ======================================================================
#define FKB 1028
#define FLASH_U2 (4 * FKB + 128 * 20)
#define FLASH_SMEM_BYTES (FLASH_U2 * 8)

__global__ __launch_bounds__(256, 2) void flash_bf16()
{
    extern __shared__ uint2 fsm[];
    uint2* Qp = fsm + 4 * FKB;

    const int tid = threadIdx.x;
    const int wid = tid >> 5;
    const int lane = tid & 31;
    const int mu = lane >> 2;
    const int la = lane & 3;
    const int b = blockIdx.z, h = blockIdx.y;
    const int q0 = blockIdx.x * 128;
    const size_t hoff = ((size_t)(b * H_NUM + h)) * S_LEN * DK_;

    const int kkk = tid & 3, kkey = tid >> 2;
    const __nv_bfloat16* ksrc = g_kb + hoff + (size_t)kkey * DK_ + kkk * 16;
    const int vkk = tid & 3, vd = tid >> 2;
    const __nv_bfloat16* vsrc = g_vTb + hoff + (size_t)vd * S_LEN + vkk * 16;
    const int kdst_i = kkk * 257 + kkey * 4;
    const int vdst_i = vkk * 257 + vd * 4;

#pragma unroll
    for (int it = 0; it < 2; it++) {
        int item = tid + it * 256;
        int row = item >> 2, kk = item & 3;
        const __nv_bfloat16* qs = g_qb + hoff + (size_t)(q0 + row) * DK_ + kk * 16;
        uint4 u0 = *(const uint4*)qs;
        uint4 u1 = *(const uint4*)(qs + 8);
        uint2* dst = Qp + row * 20 + kk * 4;
        dst[0] = make_uint2(u0.x, u1.x);
        dst[1] = make_uint2(u0.y, u1.y);
        dst[2] = make_uint2(u0.z, u1.z);
        dst[3] = make_uint2(u0.w, u1.w);
    }
    {
        uint4 k0a = *(const uint4*)ksrc;
        uint4 k0b = *(const uint4*)(ksrc + 8);
        uint4 v0a = *(const uint4*)vsrc;
        uint4 v0b = *(const uint4*)(vsrc + 8);
        uint2* kd = fsm + kdst_i;
        kd[0] = make_uint2(k0a.x, k0b.x); kd[1] = make_uint2(k0a.y, k0b.y);
        kd[2] = make_uint2(k0a.z, k0b.z); kd[3] = make_uint2(k0a.w, k0b.w);
        uint2* vdp = fsm + 2 * FKB + vdst_i;
        vdp[0] = make_uint2(v0a.x, v0b.x); vdp[1] = make_uint2(v0a.y, v0b.y);
        vdp[2] = make_uint2(v0a.z, v0b.z); vdp[3] = make_uint2(v0a.w, v0b.w);
    }
    __syncthreads();

    uint32_t qf[4][4];
    {
        const int r0 = wid * 16 + mu;
#pragma unroll
        for (int kk = 0; kk < 4; kk++) {
            uint2 qa = Qp[r0 * 20 + kk * 4 + la];
            uint2 qb = Qp[(r0 + 8) * 20 + kk * 4 + la];
            qf[kk][0] = qa.x; qf[kk][1] = qb.x;
            qf[kk][2] = qa.y; qf[kk][3] = qb.y;
        }
    }

    float m0 = -1e30f, m1 = -1e30f, l0 = 0.f, l1 = 0.f;
    float acc[8][4];
#pragma unroll
    for (int j = 0; j < 8; j++)
#pragma unroll
        for (int e = 0; e < 4; e++) acc[j][e] = 0.f;

    const int NCH = S_LEN / 64;
    for (int kt = 0; kt < NCH; kt++) {
        const uint2* Kc = fsm + (kt & 1) * FKB;
        const uint2* Vc = fsm + 2 * FKB + (kt & 1) * FKB;

        uint4 ku0, ku1, vu0, vu1;
        const bool more = (kt + 1 < NCH);
        if (more) {
            const __nv_bfloat16* ks = ksrc + (size_t)(kt + 1) * 64 * DK_;
            const __nv_bfloat16* vs = vsrc + (size_t)(kt + 1) * 64;
            ku0 = *(const uint4*)ks; ku1 = *(const uint4*)(ks + 8);
            vu0 = *(const uint4*)vs; vu1 = *(const uint4*)(vs + 8);
        }

        float s[8][4];
#pragma unroll
        for (int j = 0; j < 8; j++)
#pragma unroll
            for (int e = 0; e < 4; e++) s[j][e] = 0.f;
#pragma unroll
        for (int kk = 0; kk < 4; kk++) {
#pragma unroll
            for (int j = 0; j < 8; j++) {
                uint2 kb = Kc[kk * 257 + (j * 8 + mu) * 4 + la];
                mma_bf16(s[j], qf[kk], kb.x, kb.y);
            }
        }

        float mx0 = -1e30f, mx1 = -1e30f;
#pragma unroll
        for (int j = 0; j < 8; j++) {
            mx0 = fmaxf(mx0, fmaxf(s[j][0], s[j][1]));
            mx1 = fmaxf(mx1, fmaxf(s[j][2], s[j][3]));
        }
        mx0 = fmaxf(mx0, __shfl_xor_sync(0xffffffffu, mx0, 1));
        mx0 = fmaxf(mx0, __shfl_xor_sync(0xffffffffu, mx0, 2));
        mx1 = fmaxf(mx1, __shfl_xor_sync(0xffffffffu, mx1, 1));
        mx1 = fmaxf(mx1, __shfl_xor_sync(0xffffffffu, mx1, 2));
        const float nm0 = fmaxf(m0, mx0), nm1 = fmaxf(m1, mx1);
        float sum0 = 0.f, sum1 = 0.f;
#pragma unroll
        for (int j = 0; j < 8; j++) {
            s[j][0] = exp2f(s[j][0] - nm0);
            s[j][1] = exp2f(s[j][1] - nm0);
            s[j][2] = exp2f(s[j][2] - nm1);
            s[j][3] = exp2f(s[j][3] - nm1);
            sum0 += s[j][0] + s[j][1];
            sum1 += s[j][2] + s[j][3];
        }
        sum0 += __shfl_xor_sync(0xffffffffu, sum0, 1);
        sum0 += __shfl_xor_sync(0xffffffffu, sum0, 2);
        sum1 += __shfl_xor_sync(0xffffffffu, sum1, 1);
        sum1 += __shfl_xor_sync(0xffffffffu, sum1, 2);
        const float sc0 = exp2f(m0 - nm0), sc1 = exp2f(m1 - nm1);
#pragma unroll
        for (int j = 0; j < 8; j++) {
            acc[j][0] *= sc0; acc[j][1] *= sc0;
            acc[j][2] *= sc1; acc[j][3] *= sc1;
        }
        l0 = l0 * sc0 + sum0; l1 = l1 * sc1 + sum1;
        m0 = nm0; m1 = nm1;

        uint32_t pf[4][4];
#pragma unroll
        for (int kk = 0; kk < 4; kk++) {
            pf[kk][0] = packbf(s[2 * kk][0],     s[2 * kk][1]);
            pf[kk][1] = packbf(s[2 * kk][2],     s[2 * kk][3]);
            pf[kk][2] = packbf(s[2 * kk + 1][0], s[2 * kk + 1][1]);
            pf[kk][3] = packbf(s[2 * kk + 1][2], s[2 * kk + 1][3]);
        }

#pragma unroll
        for (int kk = 0; kk < 4; kk++) {
#pragma unroll
            for (int j = 0; j < 8; j++) {
                uint2 vb = Vc[kk * 257 + (j * 8 + mu) * 4 + la];
                mma_bf16(acc[j], pf[kk], vb.x, vb.y);
            }
        }

        if (more) {
            uint2* kd = fsm + ((kt + 1) & 1) * FKB + kdst_i;
            kd[0] = make_uint2(ku0.x, ku1.x); kd[1] = make_uint2(ku0.y, ku1.y);
            kd[2] = make_uint2(ku0.z, ku1.z); kd[3] = make_uint2(ku0.w, ku1.w);
            uint2* vdp = fsm + 2 * FKB + ((kt + 1) & 1) * FKB + vdst_i;
            vdp[0] = make_uint2(vu0.x, vu1.x); vdp[1] = make_uint2(vu0.y, vu1.y);
            vdp[2] = make_uint2(vu0.z, vu1.z); vdp[3] = make_uint2(vu0.w, vu1.w);
        }
        __syncthreads();
    }

    const float i0 = 1.f / l0, i1 = 1.f / l1;
    const int row_a = q0 + wid * 16 + mu;
    const int row_b = row_a + 8;
    __nv_bfloat16* oa = &g_attnb[((size_t)b * S_LEN + row_a) * E_DIM + h * DK_];
    __nv_bfloat16* ob = &g_attnb[((size_t)b * S_LEN + row_b) * E_DIM + h * DK_];
#pragma unroll
    for (int j = 0; j < 8; j++) {
        const int c = j * 8 + 2 * la;
        *(uint32_t*)&oa[c] = packbf(acc[j][0] * i0, acc[j][1] * i0);
        *(uint32_t*)&ob[c] = packbf(acc[j][2] * i1, acc[j][3] * i1);
    }
}

// ======================================================================
// Fused LN1 + quantum FFN + LN2 (unchanged, passing).
// ======================================================================
__global__ __launch_bounds__(256) void ln_fused(const float* __restrict__ x,
                                                const float* __restrict__ g1,
                                                const float* __restrict__ be1,
                                                const float* __restrict__ g2,
                                                const float* __restrict__ be2,
                                                const float* __restrict__ theta,
                                                const float* __restrict__ w1,
                                                const float* __restrict__ b1s,
                                                float* __restrict__ out)
{
    const int row = blockIdx.x;
    const int tid = threadIdx.x;
    const float* xr = x + (size_t)row * E_DIM;
    const float* pr = g_proj + (size_t)row * E_DIM;

    __shared__ float red[16];
    __shared__ float sx1[8];

    float4 xv = *(const float4*)&xr[tid * 4];
    float4 pv = *(const float4*)&pr[tid * 4];
    float v[4] = {xv.x + pv.x, xv.y + pv.y, xv.z + pv.z, xv.w + pv.w};

    float s = 0.f, ss = 0.f;
#pragma unroll
    for (int i = 0; i < 4; i++) { s += v[i]; ss += v[i] * v[i]; }
#pragma unroll
    for (int o = 16; o > 0; o >>= 1) {
        s  += __shfl_xor_sync(0xffffffffu, s, o);
        ss += __shfl_xor_sync(0xffffffffu, ss, o);
    }
    if ((tid & 31) == 0) { red[tid >> 5] = s; red[8 + (tid >> 5)] = ss; }
    __syncthreads();
    s = 0.f; ss = 0.f;
#pragma unroll
    for (int w = 0; w < 8; w++) { s += red[w]; ss += red[8 + w]; }
    float mean = s * (1.f / E_DIM);
    float var  = ss * (1.f / E_DIM) - mean * mean;
    float rs = rsqrtf(var + 1e-5f);

    float4 g1v = *(const float4*)&g1[tid * 4];
    float4 b1v = *(const float4*)&be1[tid * 4];
    float x1[4];
    x1[0] = (v[0] - mean) * rs * g1v.x + b1v.x;
    x1[1] = (v[1] - mean) * rs * g1v.y + b1v.y;
    x1[2] = (v[2] - mean) * rs * g1v.z + b1v.z;
    x1[3] = (v[3] - mean) * rs * g1v.w + b1v.w;
    if (tid < 2) {
#pragma unroll
        for (int i = 0; i < 4; i++) sx1[tid * 4 + i] = x1[i];
    }
    __syncthreads();

    float f = b1s[0];
#pragma unroll
    for (int q = 0; q < 8; q++) f += __cosf(sx1[q]) * __cosf(theta[q]) * w1[q];

    float y[4];
    s = 0.f; ss = 0.f;
#pragma unroll
    for (int i = 0; i < 4; i++) { y[i] = x1[i] + f; s += y[i]; ss += y[i] * y[i]; }
#pragma unroll
    for (int o = 16; o > 0; o >>= 1) {
        s  += __shfl_xor_sync(0xffffffffu, s, o);
        ss += __shfl_xor_sync(0xffffffffu, ss, o);
    }
    if ((tid & 31) == 0) { red[tid >> 5] = s; red[8 + (tid >> 5)] = ss; }
    __syncthreads();
    s = 0.f; ss = 0.f;
#pragma unroll
    for (int w = 0; w < 8; w++) { s += red[w]; ss += red[8 + w]; }
    float mean2 = s * (1.f / E_DIM);
    float var2  = ss * (1.f / E_DIM) - mean2 * mean2;
    float rs2 = rsqrtf(var2 + 1e-5f);

    float4 g2v = *(const float4*)&g2[tid * 4];
    float4 b2v = *(const float4*)&be2[tid * 4];
    float4 ov;
    ov.x = (y[0] - mean2) * rs2 * g2v.x + b2v.x;
    ov.y = (y[1] - mean2) * rs2 * g2v.y + b2v.y;
    ov.z = (y[2] - mean2) * rs2 * g2v.z + b2v.z;
    ov.w = (y[3] - mean2) * rs2 * g2v.w + b2v.w;
    *(float4*)&out[(size_t)row * E_DIM + tid * 4] = ov;
}

// ======================================================================
extern "C" void kernel_launch(void* const* d_in, const int* in_sizes, int n_in,
                              void* d_out, int out_size)
{
    const float* x      = (const float*)d_in[0];
    const float* w_qkv  = (const float*)d_in[1];
    const float* w_comb = (const float*)d_in[2];
    const float* b_comb = (const float*)d_in[3];
    const float* gamma1 = (const float*)d_in[4];
    const float* beta1  = (const float*)d_in[5];
    const float* gamma2 = (const float*)d_in[6];
    const float* beta2  = (const float*)d_in[7];
    const float* theta  = (const float*)d_in[8];
    const float* w1     = (const float*)d_in[9];
    const float* b1     = (const float*)d_in[10];

    __nv_bfloat16* xb_p;  cudaGetSymbolAddress((void**)&xb_p, g_xb);
    __nv_bfloat16* wqb_p; cudaGetSymbolAddress((void**)&wqb_p, g_wqb);
    __nv_bfloat16* wcb_p; cudaGetSymbolAddress((void**)&wcb_p, g_wcb);

    cudaFuncSetAttribute(gemm_cp<0>, cudaFuncAttributeMaxDynamicSharedMemorySize,
                         GEMM_SMEM_BYTES);
    cudaFuncSetAttribute(gemm_cp<1>, cudaFuncAttributeMaxDynamicSharedMemorySize,
                         GEMM_SMEM_BYTES);
    cudaFuncSetAttribute(flash_bf16, cudaFuncAttributeMaxDynamicSharedMemorySize,
                         FLASH_SMEM_BYTES);

    conv_bf16<<<(M_TOK * K_DIM / 8 + 255) / 256, 256>>>(x, xb_p, M_TOK * K_DIM / 8);
    conv_bf16<<<(N_QKV * K_DIM / 8 + 255) / 256, 256>>>(w_qkv, wqb_p, N_QKV * K_DIM / 8);
    conv_bf16<<<(E_DIM * K_DIM / 8 + 255) / 256, 256>>>(w_comb, wcb_p, E_DIM * K_DIM / 8);

    gemm_cp<0><<<dim3(N_QKV / 64, M_TOK / 128), 256, GEMM_SMEM_BYTES>>>(nullptr);
    flash_bf16<<<dim3(S_LEN / 128, H_NUM, B_SZ), 256, FLASH_SMEM_BYTES>>>();
    gemm_cp<1><<<dim3(E_DIM / 64, M_TOK / 128), 256, GEMM_SMEM_BYTES>>>(b_comb);
    ln_fused<<<M_TOK, 256>>>(x, gamma1, beta1, gamma2, beta2, theta, w1, b1,
                             (float*)d_out);
}

// round 12
// speedup vs baseline: 1.0170x; 1.0170x over previous
#include <cuda_runtime.h>
#include <cuda_bf16.h>
#include <cstdint>
#include <math.h>

// ---------------- problem constants ----------------
#define E_DIM  1024
#define H_NUM  16
#define DK_    64
#define B_SZ   2
#define S_LEN  2048
#define M_TOK  (B_SZ * S_LEN)
#define N_QKV  (3 * E_DIM)
#define K_DIM  1024

#define QSCALE (0.125f * 1.44269504088896f)   // 1/sqrt(dk) * log2(e)

// ---------------- device scratch (alloc-free) ----------------
__device__ __align__(16) __nv_bfloat16 g_xb[M_TOK * K_DIM];
__device__ __align__(16) __nv_bfloat16 g_wqb[N_QKV * K_DIM];
__device__ __align__(16) __nv_bfloat16 g_wcb[E_DIM * K_DIM];
__device__ __align__(16) __nv_bfloat16 g_qb[B_SZ * H_NUM * S_LEN * DK_];
__device__ __align__(16) __nv_bfloat16 g_kb[B_SZ * H_NUM * S_LEN * DK_];
__device__ __align__(16) __nv_bfloat16 g_vTb[B_SZ * H_NUM * DK_ * S_LEN];
__device__ __align__(16) __nv_bfloat16 g_attnb[M_TOK * E_DIM];
__device__ __align__(16) __nv_bfloat16 g_projb[M_TOK * E_DIM];   // bf16 now

__device__ __forceinline__ uint32_t packbf(float lo, float hi) {
    uint32_t r;
    asm("cvt.rn.bf16x2.f32 %0, %1, %2;" : "=r"(r) : "f"(hi), "f"(lo));
    return r;
}
__device__ __forceinline__ void mma_bf16(float c[4], const uint32_t a[4],
                                         const uint32_t b0, const uint32_t b1) {
    asm volatile(
        "mma.sync.aligned.m16n8k16.row.col.f32.bf16.bf16.f32 "
        "{%0,%1,%2,%3}, {%4,%5,%6,%7}, {%8,%9}, {%0,%1,%2,%3};"
        : "+f"(c[0]), "+f"(c[1]), "+f"(c[2]), "+f"(c[3])
        : "r"(a[0]), "r"(a[1]), "r"(a[2]), "r"(a[3]), "r"(b0), "r"(b1));
}
__device__ __forceinline__ void ldm_x4(uint32_t& r0, uint32_t& r1,
                                       uint32_t& r2, uint32_t& r3, uint32_t a) {
    asm volatile("ldmatrix.sync.aligned.m8n8.x4.shared.b16 {%0,%1,%2,%3}, [%4];"
                 : "=r"(r0), "=r"(r1), "=r"(r2), "=r"(r3) : "r"(a));
}
__device__ __forceinline__ void cp16(uint32_t dst, const void* src) {
    asm volatile("cp.async.cg.shared.global [%0], [%1], 16;"
                 :: "r"(dst), "l"(src));
}
#define CP_COMMIT() asm volatile("cp.async.commit_group;")
#define CP_WAIT1()  asm volatile("cp.async.wait_group 1;")

// ======================================================================
// fp32 -> bf16 bulk convert
// ======================================================================
__global__ __launch_bounds__(256) void conv_bf16(const float* __restrict__ src,
                                                 __nv_bfloat16* __restrict__ dst,
                                                 int n8)
{
    int i = blockIdx.x * 256 + threadIdx.x;
    if (i >= n8) return;
    float4 a = *(const float4*)&src[i * 8];
    float4 b = *(const float4*)&src[i * 8 + 4];
    uint4 o = make_uint4(packbf(a.x, a.y), packbf(a.z, a.w),
                         packbf(b.x, b.y), packbf(b.z, b.w));
    *(uint4*)&dst[i * 8] = o;
}

// ======================================================================
// bf16 GEMM (round-10 config — best known): CTA 128x128, BK=32,
// 3-stage cp.async + ldmatrix.  8 warps (2m x 4n), warp tile 64x32.
// Smem row 80B (64B data + 16B pad): (5*row+chunk)%8 -> conflict-free.
// MODE 0: A=g_xb, W=g_wqb -> g_qb(xQSCALE)/g_kb/g_vTb
// MODE 1: A=g_attnb, W=g_wcb, +bias -> bf16 g_projb
// ======================================================================
#define ROWB 80
#define MATB (128 * ROWB)
#define STAGEB (2 * MATB)
#define NSTAGE 3
#define GEMM_SMEM_BYTES (NSTAGE * STAGEB)  // 61440

template <int MODE>
__global__ __launch_bounds__(256) void gemm_cp(const float* __restrict__ bias)
{
    extern __shared__ char sm[];
    const uint32_t smbase = (uint32_t)__cvta_generic_to_shared(sm);

    const __nv_bfloat16* __restrict__ A = (MODE == 1) ? g_attnb : g_xb;
    const __nv_bfloat16* __restrict__ W = (MODE == 1) ? g_wcb : g_wqb;

    const int tid = threadIdx.x;
    const int wid = tid >> 5;
    const int lane = tid & 31;
    const int mu = lane >> 2;
    const int la = lane & 3;
    const int warp_m = wid & 1;
    const int warp_n = wid >> 1;
    const int m0 = blockIdx.y * 128;
    const int n0 = blockIdx.x * 128;

    const int st_row = tid >> 1;
    const int st_c   = (tid & 1) * 2;
    const __nv_bfloat16* asrc = &A[(size_t)(m0 + st_row) * K_DIM + st_c * 8];
    const __nv_bfloat16* wsrc = &W[(size_t)(n0 + st_row) * K_DIM + st_c * 8];
    const uint32_t st_off = (uint32_t)(st_row * ROWB + st_c * 16);

    const int lrow = lane & 15;
    const int lchunk = lane >> 4;

    float acc[4][4][4];
#pragma unroll
    for (int mt = 0; mt < 4; mt++)
#pragma unroll
        for (int nt = 0; nt < 4; nt++)
#pragma unroll
            for (int e = 0; e < 4; e++) acc[mt][nt][e] = 0.f;

    const int NK = K_DIM / 32;

#pragma unroll
    for (int t = 0; t < NSTAGE - 1; t++) {
        uint32_t ad = smbase + t * STAGEB + st_off;
        cp16(ad,      asrc + t * 32);
        cp16(ad + 16, asrc + t * 32 + 8);
        cp16(ad + MATB,      wsrc + t * 32);
        cp16(ad + MATB + 16, wsrc + t * 32 + 8);
        CP_COMMIT();
    }

    for (int t = 0; t < NK; t++) {
        CP_WAIT1();
        __syncthreads();

        if (t + NSTAGE - 1 < NK) {
            const int tt = t + NSTAGE - 1;
            uint32_t ad = smbase + (tt % NSTAGE) * STAGEB + st_off;
            cp16(ad,      asrc + tt * 32);
            cp16(ad + 16, asrc + tt * 32 + 8);
            cp16(ad + MATB,      wsrc + tt * 32);
            cp16(ad + MATB + 16, wsrc + tt * 32 + 8);
        }
        CP_COMMIT();

        const uint32_t abase = smbase + (t % NSTAGE) * STAGEB;
        const uint32_t bbase = abase + MATB;

#pragma unroll
        for (int kk = 0; kk < 2; kk++) {
            uint32_t afr[4][4];
#pragma unroll
            for (int mt = 0; mt < 4; mt++) {
                const int row = warp_m * 64 + mt * 16 + lrow;
                ldm_x4(afr[mt][0], afr[mt][1], afr[mt][2], afr[mt][3],
                       abase + row * ROWB + (kk * 2 + lchunk) * 16);
            }
            uint32_t bfr[4][2];
#pragma unroll
            for (int np = 0; np < 2; np++) {
                const int row = warp_n * 32 + np * 16 + lrow;
                uint32_t b0, b1, b2, b3;
                ldm_x4(b0, b1, b2, b3,
                       bbase + row * ROWB + (kk * 2 + lchunk) * 16);
                bfr[2 * np][0] = b0;     bfr[2 * np][1] = b2;
                bfr[2 * np + 1][0] = b1; bfr[2 * np + 1][1] = b3;
            }
#pragma unroll
            for (int mt = 0; mt < 4; mt++)
#pragma unroll
                for (int nt = 0; nt < 4; nt++)
                    mma_bf16(acc[mt][nt], afr[mt], bfr[nt][0], bfr[nt][1]);
        }
        __syncthreads();
    }

    // ---- epilogue ----
#pragma unroll
    for (int mt = 0; mt < 4; mt++) {
        const int m_lo = m0 + warp_m * 64 + mt * 16 + mu;
        const int m_hi = m_lo + 8;
#pragma unroll
        for (int nt = 0; nt < 4; nt++) {
            const int n = n0 + warp_n * 32 + nt * 8 + 2 * la;
            if (MODE == 0) {
                const int which = n >> 10;
                const int h = (n >> 6) & 15;
                const int d0 = n & 63;
                const int b = m_lo >> 11;
                const int s_lo = m_lo & 2047, s_hi = m_hi & 2047;
                if (which == 0) {
                    size_t base = (((size_t)(b * H_NUM + h)) * S_LEN);
                    *(uint32_t*)&g_qb[(base + s_lo) * DK_ + d0] =
                        packbf(acc[mt][nt][0] * QSCALE, acc[mt][nt][1] * QSCALE);
                    *(uint32_t*)&g_qb[(base + s_hi) * DK_ + d0] =
                        packbf(acc[mt][nt][2] * QSCALE, acc[mt][nt][3] * QSCALE);
                } else if (which == 1) {
                    size_t base = (((size_t)(b * H_NUM + h)) * S_LEN);
                    *(uint32_t*)&g_kb[(base + s_lo) * DK_ + d0] =
                        packbf(acc[mt][nt][0], acc[mt][nt][1]);
                    *(uint32_t*)&g_kb[(base + s_hi) * DK_ + d0] =
                        packbf(acc[mt][nt][2], acc[mt][nt][3]);
                } else {
                    size_t base = (((size_t)(b * H_NUM + h)) * DK_ + d0) * S_LEN;
                    g_vTb[base + s_lo]          = __float2bfloat16_rn(acc[mt][nt][0]);
                    g_vTb[base + S_LEN + s_lo]  = __float2bfloat16_rn(acc[mt][nt][1]);
                    g_vTb[base + s_hi]          = __float2bfloat16_rn(acc[mt][nt][2]);
                    g_vTb[base + S_LEN + s_hi]  = __float2bfloat16_rn(acc[mt][nt][3]);
                }
            } else {
                const float b0 = bias[n], b1 = bias[n + 1];
                *(uint32_t*)&g_projb[(size_t)m_lo * E_DIM + n] =
                    packbf(acc[mt][nt][0] + b0, acc[mt][nt][1] + b1);
                *(uint32_t*)&g_projb[(size_t)m_hi * E_DIM + n] =
                    packbf(acc[mt][nt][2] + b0, acc[mt][nt][3] + b1);
            }
        }
    }
}

// ======================================================================
// Flash attention, bf16 m16n8k16, register-resident P, exp2 softmax,
// warp-voted rescale skip. Output bf16 -> g_attnb.
// ======================================================================
#define FKB 1028
#define FLASH_U2 (4 * FKB + 128 * 20)
#define FLASH_SMEM_BYTES (FLASH_U2 * 8)

__global__ __launch_bounds__(256, 2) void flash_bf16()
{
    extern __shared__ uint2 fsm[];
    uint2* Qp = fsm + 4 * FKB;

    const int tid = threadIdx.x;
    const int wid = tid >> 5;
    const int lane = tid & 31;
    const int mu = lane >> 2;
    const int la = lane & 3;
    const int b = blockIdx.z, h = blockIdx.y;
    const int q0 = blockIdx.x * 128;
    const size_t hoff = ((size_t)(b * H_NUM + h)) * S_LEN * DK_;

    const int kkk = tid & 3, kkey = tid >> 2;
    const __nv_bfloat16* ksrc = g_kb + hoff + (size_t)kkey * DK_ + kkk * 16;
    const int vkk = tid & 3, vd = tid >> 2;
    const __nv_bfloat16* vsrc = g_vTb + hoff + (size_t)vd * S_LEN + vkk * 16;
    const int kdst_i = kkk * 257 + kkey * 4;
    const int vdst_i = vkk * 257 + vd * 4;

#pragma unroll
    for (int it = 0; it < 2; it++) {
        int item = tid + it * 256;
        int row = item >> 2, kk = item & 3;
        const __nv_bfloat16* qs = g_qb + hoff + (size_t)(q0 + row) * DK_ + kk * 16;
        uint4 u0 = *(const uint4*)qs;
        uint4 u1 = *(const uint4*)(qs + 8);
        uint2* dst = Qp + row * 20 + kk * 4;
        dst[0] = make_uint2(u0.x, u1.x);
        dst[1] = make_uint2(u0.y, u1.y);
        dst[2] = make_uint2(u0.z, u1.z);
        dst[3] = make_uint2(u0.w, u1.w);
    }
    {
        uint4 k0a = *(const uint4*)ksrc;
        uint4 k0b = *(const uint4*)(ksrc + 8);
        uint4 v0a = *(const uint4*)vsrc;
        uint4 v0b = *(const uint4*)(vsrc + 8);
        uint2* kd = fsm + kdst_i;
        kd[0] = make_uint2(k0a.x, k0b.x); kd[1] = make_uint2(k0a.y, k0b.y);
        kd[2] = make_uint2(k0a.z, k0b.z); kd[3] = make_uint2(k0a.w, k0b.w);
        uint2* vdp = fsm + 2 * FKB + vdst_i;
        vdp[0] = make_uint2(v0a.x, v0b.x); vdp[1] = make_uint2(v0a.y, v0b.y);
        vdp[2] = make_uint2(v0a.z, v0b.z); vdp[3] = make_uint2(v0a.w, v0b.w);
    }
    __syncthreads();

    uint32_t qf[4][4];
    {
        const int r0 = wid * 16 + mu;
#pragma unroll
        for (int kk = 0; kk < 4; kk++) {
            uint2 qa = Qp[r0 * 20 + kk * 4 + la];
            uint2 qb = Qp[(r0 + 8) * 20 + kk * 4 + la];
            qf[kk][0] = qa.x; qf[kk][1] = qb.x;
            qf[kk][2] = qa.y; qf[kk][3] = qb.y;
        }
    }

    float m0 = -1e30f, m1 = -1e30f, l0 = 0.f, l1 = 0.f;
    float acc[8][4];
#pragma unroll
    for (int j = 0; j < 8; j++)
#pragma unroll
        for (int e = 0; e < 4; e++) acc[j][e] = 0.f;

    const int NCH = S_LEN / 64;
    for (int kt = 0; kt < NCH; kt++) {
        const uint2* Kc = fsm + (kt & 1) * FKB;
        const uint2* Vc = fsm + 2 * FKB + (kt & 1) * FKB;

        uint4 ku0, ku1, vu0, vu1;
        const bool more = (kt + 1 < NCH);
        if (more) {
            const __nv_bfloat16* ks = ksrc + (size_t)(kt + 1) * 64 * DK_;
            const __nv_bfloat16* vs = vsrc + (size_t)(kt + 1) * 64;
            ku0 = *(const uint4*)ks; ku1 = *(const uint4*)(ks + 8);
            vu0 = *(const uint4*)vs; vu1 = *(const uint4*)(vs + 8);
        }

        float s[8][4];
#pragma unroll
        for (int j = 0; j < 8; j++)
#pragma unroll
            for (int e = 0; e < 4; e++) s[j][e] = 0.f;
#pragma unroll
        for (int kk = 0; kk < 4; kk++) {
#pragma unroll
            for (int j = 0; j < 8; j++) {
                uint2 kb = Kc[kk * 257 + (j * 8 + mu) * 4 + la];
                mma_bf16(s[j], qf[kk], kb.x, kb.y);
            }
        }

        float mx0 = -1e30f, mx1 = -1e30f;
#pragma unroll
        for (int j = 0; j < 8; j++) {
            mx0 = fmaxf(mx0, fmaxf(s[j][0], s[j][1]));
            mx1 = fmaxf(mx1, fmaxf(s[j][2], s[j][3]));
        }
        mx0 = fmaxf(mx0, __shfl_xor_sync(0xffffffffu, mx0, 1));
        mx0 = fmaxf(mx0, __shfl_xor_sync(0xffffffffu, mx0, 2));
        mx1 = fmaxf(mx1, __shfl_xor_sync(0xffffffffu, mx1, 1));
        mx1 = fmaxf(mx1, __shfl_xor_sync(0xffffffffu, mx1, 2));
        const float nm0 = fmaxf(m0, mx0), nm1 = fmaxf(m1, mx1);
        float sum0 = 0.f, sum1 = 0.f;
#pragma unroll
        for (int j = 0; j < 8; j++) {
            s[j][0] = exp2f(s[j][0] - nm0);
            s[j][1] = exp2f(s[j][1] - nm0);
            s[j][2] = exp2f(s[j][2] - nm1);
            s[j][3] = exp2f(s[j][3] - nm1);
            sum0 += s[j][0] + s[j][1];
            sum1 += s[j][2] + s[j][3];
        }
        sum0 += __shfl_xor_sync(0xffffffffu, sum0, 1);
        sum0 += __shfl_xor_sync(0xffffffffu, sum0, 2);
        sum1 += __shfl_xor_sync(0xffffffffu, sum1, 1);
        sum1 += __shfl_xor_sync(0xffffffffu, sum1, 2);

        // warp-voted rescale skip: if NO lane's max moved, sc == 1 exactly.
        const bool moved = (nm0 != m0) | (nm1 != m1);
        if (__any_sync(0xffffffffu, moved)) {
            const float sc0 = exp2f(m0 - nm0), sc1 = exp2f(m1 - nm1);
#pragma unroll
            for (int j = 0; j < 8; j++) {
                acc[j][0] *= sc0; acc[j][1] *= sc0;
                acc[j][2] *= sc1; acc[j][3] *= sc1;
            }
            l0 = l0 * sc0 + sum0; l1 = l1 * sc1 + sum1;
            m0 = nm0; m1 = nm1;
        } else {
            l0 += sum0; l1 += sum1;
        }

        uint32_t pf[4][4];
#pragma unroll
        for (int kk = 0; kk < 4; kk++) {
            pf[kk][0] = packbf(s[2 * kk][0],     s[2 * kk][1]);
            pf[kk][1] = packbf(s[2 * kk][2],     s[2 * kk][3]);
            pf[kk][2] = packbf(s[2 * kk + 1][0], s[2 * kk + 1][1]);
            pf[kk][3] = packbf(s[2 * kk + 1][2], s[2 * kk + 1][3]);
        }

#pragma unroll
        for (int kk = 0; kk < 4; kk++) {
#pragma unroll
            for (int j = 0; j < 8; j++) {
                uint2 vb = Vc[kk * 257 + (j * 8 + mu) * 4 + la];
                mma_bf16(acc[j], pf[kk], vb.x, vb.y);
            }
        }

        if (more) {
            uint2* kd = fsm + ((kt + 1) & 1) * FKB + kdst_i;
            kd[0] = make_uint2(ku0.x, ku1.x); kd[1] = make_uint2(ku0.y, ku1.y);
            kd[2] = make_uint2(ku0.z, ku1.z); kd[3] = make_uint2(ku0.w, ku1.w);
            uint2* vdp = fsm + 2 * FKB + ((kt + 1) & 1) * FKB + vdst_i;
            vdp[0] = make_uint2(vu0.x, vu1.x); vdp[1] = make_uint2(vu0.y, vu1.y);
            vdp[2] = make_uint2(vu0.z, vu1.z); vdp[3] = make_uint2(vu0.w, vu1.w);
        }
        __syncthreads();
    }

    const float i0 = 1.f / l0, i1 = 1.f / l1;
    const int row_a = q0 + wid * 16 + mu;
    const int row_b = row_a + 8;
    __nv_bfloat16* oa = &g_attnb[((size_t)b * S_LEN + row_a) * E_DIM + h * DK_];
    __nv_bfloat16* ob = &g_attnb[((size_t)b * S_LEN + row_b) * E_DIM + h * DK_];
#pragma unroll
    for (int j = 0; j < 8; j++) {
        const int c = j * 8 + 2 * la;
        *(uint32_t*)&oa[c] = packbf(acc[j][0] * i0, acc[j][1] * i0);
        *(uint32_t*)&ob[c] = packbf(acc[j][2] * i1, acc[j][3] * i1);
    }
}

// ======================================================================
// Fused LN1 + quantum FFN + LN2; proj read as bf16.
// ======================================================================
__global__ __launch_bounds__(256) void ln_fused(const float* __restrict__ x,
                                                const float* __restrict__ g1,
                                                const float* __restrict__ be1,
                                                const float* __restrict__ g2,
                                                const float* __restrict__ be2,
                                                const float* __restrict__ theta,
                                                const float* __restrict__ w1,
                                                const float* __restrict__ b1s,
                                                float* __restrict__ out)
{
    const int row = blockIdx.x;
    const int tid = threadIdx.x;
    const float* xr = x + (size_t)row * E_DIM;
    const __nv_bfloat16* pr = g_projb + (size_t)row * E_DIM;

    __shared__ float red[16];
    __shared__ float sx1[8];

    float4 xv = *(const float4*)&xr[tid * 4];
    uint2 pu = *(const uint2*)&pr[tid * 4];
    float2 p01 = __bfloat1622float2(*(const __nv_bfloat162*)&pu.x);
    float2 p23 = __bfloat1622float2(*(const __nv_bfloat162*)&pu.y);
    float v[4] = {xv.x + p01.x, xv.y + p01.y, xv.z + p23.x, xv.w + p23.y};

    float s = 0.f, ss = 0.f;
#pragma unroll
    for (int i = 0; i < 4; i++) { s += v[i]; ss += v[i] * v[i]; }
#pragma unroll
    for (int o = 16; o > 0; o >>= 1) {
        s  += __shfl_xor_sync(0xffffffffu, s, o);
        ss += __shfl_xor_sync(0xffffffffu, ss, o);
    }
    if ((tid & 31) == 0) { red[tid >> 5] = s; red[8 + (tid >> 5)] = ss; }
    __syncthreads();
    s = 0.f; ss = 0.f;
#pragma unroll
    for (int w = 0; w < 8; w++) { s += red[w]; ss += red[8 + w]; }
    float mean = s * (1.f / E_DIM);
    float var  = ss * (1.f / E_DIM) - mean * mean;
    float rs = rsqrtf(var + 1e-5f);

    float4 g1v = *(const float4*)&g1[tid * 4];
    float4 b1v = *(const float4*)&be1[tid * 4];
    float x1[4];
    x1[0] = (v[0] - mean) * rs * g1v.x + b1v.x;
    x1[1] = (v[1] - mean) * rs * g1v.y + b1v.y;
    x1[2] = (v[2] - mean) * rs * g1v.z + b1v.z;
    x1[3] = (v[3] - mean) * rs * g1v.w + b1v.w;
    if (tid < 2) {
#pragma unroll
        for (int i = 0; i < 4; i++) sx1[tid * 4 + i] = x1[i];
    }
    __syncthreads();

    float f = b1s[0];
#pragma unroll
    for (int q = 0; q < 8; q++) f += __cosf(sx1[q]) * __cosf(theta[q]) * w1[q];

    float y[4];
    s = 0.f; ss = 0.f;
#pragma unroll
    for (int i = 0; i < 4; i++) { y[i] = x1[i] + f; s += y[i]; ss += y[i] * y[i]; }
#pragma unroll
    for (int o = 16; o > 0; o >>= 1) {
        s  += __shfl_xor_sync(0xffffffffu, s, o);
        ss += __shfl_xor_sync(0xffffffffu, ss, o);
    }
    if ((tid & 31) == 0) { red[tid >> 5] = s; red[8 + (tid >> 5)] = ss; }
    __syncthreads();
    s = 0.f; ss = 0.f;
#pragma unroll
    for (int w = 0; w < 8; w++) { s += red[w]; ss += red[8 + w]; }
    float mean2 = s * (1.f / E_DIM);
    float var2  = ss * (1.f / E_DIM) - mean2 * mean2;
    float rs2 = rsqrtf(var2 + 1e-5f);

    float4 g2v = *(const float4*)&g2[tid * 4];
    float4 b2v = *(const float4*)&be2[tid * 4];
    float4 ov;
    ov.x = (y[0] - mean2) * rs2 * g2v.x + b2v.x;
    ov.y = (y[1] - mean2) * rs2 * g2v.y + b2v.y;
    ov.z = (y[2] - mean2) * rs2 * g2v.z + b2v.z;
    ov.w = (y[3] - mean2) * rs2 * g2v.w + b2v.w;
    *(float4*)&out[(size_t)row * E_DIM + tid * 4] = ov;
}

// ======================================================================
extern "C" void kernel_launch(void* const* d_in, const int* in_sizes, int n_in,
                              void* d_out, int out_size)
{
    const float* x      = (const float*)d_in[0];
    const float* w_qkv  = (const float*)d_in[1];
    const float* w_comb = (const float*)d_in[2];
    const float* b_comb = (const float*)d_in[3];
    const float* gamma1 = (const float*)d_in[4];
    const float* beta1  = (const float*)d_in[5];
    const float* gamma2 = (const float*)d_in[6];
    const float* beta2  = (const float*)d_in[7];
    const float* theta  = (const float*)d_in[8];
    const float* w1     = (const float*)d_in[9];
    const float* b1     = (const float*)d_in[10];

    __nv_bfloat16* xb_p;  cudaGetSymbolAddress((void**)&xb_p, g_xb);
    __nv_bfloat16* wqb_p; cudaGetSymbolAddress((void**)&wqb_p, g_wqb);
    __nv_bfloat16* wcb_p; cudaGetSymbolAddress((void**)&wcb_p, g_wcb);

    cudaFuncSetAttribute(gemm_cp<0>, cudaFuncAttributeMaxDynamicSharedMemorySize,
                         GEMM_SMEM_BYTES);
    cudaFuncSetAttribute(gemm_cp<1>, cudaFuncAttributeMaxDynamicSharedMemorySize,
                         GEMM_SMEM_BYTES);
    cudaFuncSetAttribute(flash_bf16, cudaFuncAttributeMaxDynamicSharedMemorySize,
                         FLASH_SMEM_BYTES);

    conv_bf16<<<(M_TOK * K_DIM / 8 + 255) / 256, 256>>>(x, xb_p, M_TOK * K_DIM / 8);
    conv_bf16<<<(N_QKV * K_DIM / 8 + 255) / 256, 256>>>(w_qkv, wqb_p, N_QKV * K_DIM / 8);
    conv_bf16<<<(E_DIM * K_DIM / 8 + 255) / 256, 256>>>(w_comb, wcb_p, E_DIM * K_DIM / 8);

    gemm_cp<0><<<dim3(N_QKV / 128, M_TOK / 128), 256, GEMM_SMEM_BYTES>>>(nullptr);
    flash_bf16<<<dim3(S_LEN / 128, H_NUM, B_SZ), 256, FLASH_SMEM_BYTES>>>();
    gemm_cp<1><<<dim3(E_DIM / 128, M_TOK / 128), 256, GEMM_SMEM_BYTES>>>(b_comb);
    ln_fused<<<M_TOK, 256>>>(x, gamma1, beta1, gamma2, beta2, theta, w1, b1,
                             (float*)d_out);
}